// round 14
// baseline (speedup 1.0000x reference)
#include <cuda_runtime.h>
#include <math.h>

#define BB   4
#define TT   2048
#define CC   1024
#define NH   16
#define NKV  4
#define HD   64
#define NTOK (BB*TT)
#define GATE_CH 12

// ---------------- scratch ----------------------------------------------------
__device__ float g_qraw[NTOK*CC];
__device__ float g_kraw[NTOK*NKV*HD];
__device__ float g_vraw[NTOK*NKV*HD];
__device__ float g_gate[NTOK*NKV];
__device__ float g_qn[NTOK*CC];          // [B,H,T,D] tf32, scale*log2e folded
__device__ float g_kn[NTOK*NKV*HD];      // [B,KV,T,D] tf32
__device__ float g_vt[NTOK*NKV*HD];      // [B,KV,D,T] tf32
__device__ float g_att[NTOK*CC];         // [B,T,H*D] tf32
__device__ float g_xr[NTOK*CC];
__device__ float g_wqr[CC*CC];
__device__ float g_wkr[NKV*HD*CC];
__device__ float g_wvr[NKV*HD*CC];
__device__ float g_wor[CC*CC];

// ---------------- helpers ----------------------------------------------------
__device__ __forceinline__ unsigned f2tf(float f) {
    unsigned u;
    asm("cvt.rna.tf32.f32 %0, %1;" : "=r"(u) : "f"(f));
    return u;
}
__device__ __forceinline__ float f2tff(float f) { return __uint_as_float(f2tf(f)); }
__device__ __forceinline__ void mma_tf32(float& d0, float& d1, float& d2, float& d3,
                                         unsigned a0, unsigned a1, unsigned a2, unsigned a3,
                                         unsigned b0, unsigned b1) {
    asm volatile(
        "mma.sync.aligned.m16n8k8.row.col.f32.tf32.tf32.f32 "
        "{%0,%1,%2,%3}, {%4,%5,%6,%7}, {%8,%9}, {%0,%1,%2,%3};"
        : "+f"(d0), "+f"(d1), "+f"(d2), "+f"(d3)
        : "r"(a0), "r"(a1), "r"(a2), "r"(a3), "r"(b0), "r"(b1));
}
__device__ __forceinline__ void ldsm4(unsigned& r0, unsigned& r1, unsigned& r2, unsigned& r3,
                                      const float* p) {
    unsigned a = (unsigned)__cvta_generic_to_shared(p);
    asm volatile("ldmatrix.sync.aligned.m8n8.x4.shared.b16 {%0,%1,%2,%3}, [%4];"
                 : "=r"(r0), "=r"(r1), "=r"(r2), "=r"(r3) : "r"(a));
}
__device__ __forceinline__ void cpa16(float* s, const float* g) {
    unsigned sa = (unsigned)__cvta_generic_to_shared(s);
    asm volatile("cp.async.cg.shared.global [%0], [%1], 16;" :: "r"(sa), "l"(g));
}
__device__ __forceinline__ void cp_commit() { asm volatile("cp.async.commit_group;"); }
template<int N> __device__ __forceinline__ void cp_wait() {
    asm volatile("cp.async.wait_group %0;" :: "n"(N));
}

// ---------------- one-shot tf32 rounding of all GEMM inputs ------------------
#define N4_X  (NTOK*CC/4)
#define N4_WQ (CC*CC/4)
#define N4_WK (NKV*HD*CC/4)
__global__ void cvt_all(const float4* __restrict__ x,  const float4* __restrict__ wq,
                        const float4* __restrict__ wk, const float4* __restrict__ wv,
                        const float4* __restrict__ wo) {
    const int total = N4_X + 2 * N4_WQ + 2 * N4_WK;
    int i = blockIdx.x * blockDim.x + threadIdx.x;
    const int str = gridDim.x * blockDim.x;
    for (; i < total; i += str) {
        const float4* s; float4* d; int off = i;
        if (off < N4_X) { s = x; d = (float4*)g_xr; }
        else if ((off -= N4_X) < N4_WQ) { s = wq; d = (float4*)g_wqr; }
        else if ((off -= N4_WQ) < N4_WK) { s = wk; d = (float4*)g_wkr; }
        else if ((off -= N4_WK) < N4_WK) { s = wv; d = (float4*)g_wvr; }
        else { off -= N4_WK; s = wo; d = (float4*)g_wor; }
        float4 v = s[off];
        d[off] = make_float4(f2tff(v.x), f2tff(v.y), f2tff(v.z), f2tff(v.w));
    }
}

// ---------------- tf32 NT GEMM body (3-stage cp.async, 4 warps) --------------
// block 128x128, BK=32, 128 threads = 4 warps (2m x 2n), warp tile 64x64.
#define GS 36
#define GSTG (128*GS)
__device__ __forceinline__ void gemm_body(const float* __restrict__ A,
                                          const float* __restrict__ W,
                                          float* __restrict__ out,
                                          int N, int K, int m0, int n0) {
    extern __shared__ float gsm[];
    float* smA = gsm;
    float* smB = gsm + 3 * GSTG;

    const int tid  = threadIdx.x;       // 0..127
    const int lane = tid & 31;
    const int wid  = tid >> 5;          // 0..3
    const int wm = (wid >> 1) * 64, wn = (wid & 1) * 64;
    const int g = lane >> 2, t = lane & 3;

    const int aoff = (wm + (lane & 15)) * GS + (lane >> 4) * 4;
    const int boff = (wn + (lane & 7) + ((lane >> 4) << 3)) * GS + ((lane >> 3) & 1) * 4;

    float acc[4][8][4];
#pragma unroll
    for (int i = 0; i < 4; i++)
#pragma unroll
        for (int j = 0; j < 8; j++)
#pragma unroll
            for (int e = 0; e < 4; e++) acc[i][j][e] = 0.f;

    const int nt = K / 32;
#pragma unroll
    for (int p = 0; p < 2; p++) {
        int k0 = p * 32;
#pragma unroll
        for (int l = 0; l < 8; l++) {
            int idx = tid + l * 128;
            int row = idx >> 3, c = idx & 7;
            cpa16(&smA[p * GSTG + row * GS + c * 4], A + (size_t)(m0 + row) * K + k0 + c * 4);
            cpa16(&smB[p * GSTG + row * GS + c * 4], W + (size_t)(n0 + row) * K + k0 + c * 4);
        }
        cp_commit();
    }
    cp_wait<1>();
    __syncthreads();

    int s = 0;
    for (int i = 0; i < nt; i++) {
        if (i + 2 < nt) {
            int k0 = (i + 2) * 32;
            int sn = (s + 2) % 3;
#pragma unroll
            for (int l = 0; l < 8; l++) {
                int idx = tid + l * 128;
                int row = idx >> 3, c = idx & 7;
                cpa16(&smA[sn * GSTG + row * GS + c * 4], A + (size_t)(m0 + row) * K + k0 + c * 4);
                cpa16(&smB[sn * GSTG + row * GS + c * 4], W + (size_t)(n0 + row) * K + k0 + c * 4);
            }
            cp_commit();
        }
        const float* pA = smA + s * GSTG + aoff;
        const float* pB = smB + s * GSTG + boff;
#pragma unroll
        for (int ks = 0; ks < 4; ks++) {
            const int kk = ks * 8;
            unsigned a[4][4];
#pragma unroll
            for (int ii = 0; ii < 4; ii++)
                ldsm4(a[ii][0], a[ii][1], a[ii][2], a[ii][3], pA + ii * 16 * GS + kk);
            unsigned b[8][2];
#pragma unroll
            for (int jp = 0; jp < 4; jp++)
                ldsm4(b[2*jp][0], b[2*jp][1], b[2*jp+1][0], b[2*jp+1][1],
                      pB + jp * 16 * GS + kk);
#pragma unroll
            for (int ii = 0; ii < 4; ii++)
#pragma unroll
                for (int j = 0; j < 8; j++)
                    mma_tf32(acc[ii][j][0], acc[ii][j][1], acc[ii][j][2], acc[ii][j][3],
                             a[ii][0], a[ii][1], a[ii][2], a[ii][3], b[j][0], b[j][1]);
        }
        if (i + 2 < nt) cp_wait<1>(); else cp_wait<0>();
        __syncthreads();
        s = (s + 1) % 3;
    }
#pragma unroll
    for (int i = 0; i < 4; i++) {
        int r = m0 + wm + i * 16 + g;
#pragma unroll
        for (int j = 0; j < 8; j++) {
            int c = n0 + wn + j * 8 + 2 * t;
            *(float2*)(out + (size_t)r * N + c) = make_float2(acc[i][j][0], acc[i][j][1]);
            *(float2*)(out + (size_t)(r + 8) * N + c) = make_float2(acc[i][j][2], acc[i][j][3]);
        }
    }
}

__global__ __launch_bounds__(128) void gemm_qkv() {
    const int bid = blockIdx.x;
    if (bid < 512) {
        gemm_body(g_xr, g_wqr, g_qraw, CC, CC, (bid >> 3) * 128, (bid & 7) * 128);
    } else {
        const int r = bid - 512;
        const bool isv = (r & 3) >= 2;
        gemm_body(g_xr, isv ? g_wvr : g_wkr, isv ? g_vraw : g_kraw,
                  NKV * HD, CC, (r >> 2) * 128, (r & 1) * 128);
    }
}

__global__ __launch_bounds__(128) void gemm_tf32(const float* __restrict__ A,
                                                 const float* __restrict__ W,
                                                 float* __restrict__ out,
                                                 int N, int K) {
    gemm_body(A, W, out, N, K, blockIdx.y * 128, blockIdx.x * 128);
}

// ---------------- rotary + rmsnorm + gate ------------------------------------
__device__ __forceinline__ void rope_norm(const float* __restrict__ in,
                                          float* __restrict__ outp,
                                          int t, int lane, float mult,
                                          const float* __restrict__ cosp,
                                          const float* __restrict__ sinp) {
    float x1 = in[lane];
    float x2 = in[32 + lane];
    float c  = cosp[t * 32 + lane];
    float s  = sinp[t * 32 + lane];
    float o1 =  x1 * c + x2 * s;
    float o2 = -x1 * s + x2 * c;
    float ss = o1 * o1 + o2 * o2;
#pragma unroll
    for (int off = 16; off; off >>= 1) ss += __shfl_xor_sync(0xffffffffu, ss, off);
    float r = rsqrtf(ss * (1.0f / HD) + 1e-6f) * mult;
    outp[lane]      = f2tff(o1 * r);
    outp[32 + lane] = f2tff(o2 * r);
}

__global__ __launch_bounds__(256) void postproc(const float* __restrict__ x,
                                                const float* __restrict__ cosp,
                                                const float* __restrict__ sinp,
                                                const float* __restrict__ wgate) {
    const int n = blockIdx.x;
    const int b = n / TT;
    const int t = n % TT;
    const int w    = threadIdx.x >> 5;
    const int lane = threadIdx.x & 31;

    const float QMULT = 1.15f * 0.125f * 1.4426950408889634f;
#pragma unroll
    for (int h = w; h < NH; h += 8) {
        size_t obase = (((size_t)b * NH + h) * TT + t) * HD;
        rope_norm(g_qraw + (size_t)n * CC + h * HD, g_qn + obase, t, lane, QMULT, cosp, sinp);
    }
    if (w < 4) {
        int h = w;
        size_t obase = (((size_t)b * NKV + h) * TT + t) * HD;
        rope_norm(g_kraw + (size_t)n * NKV * HD + h * HD, g_kn + obase, t, lane,
                  1.15f, cosp, sinp);
    } else {
        int h = w - 4;
        float g = (lane < GATE_CH)
                    ? x[(size_t)n * CC + lane] * wgate[h * GATE_CH + lane] : 0.f;
#pragma unroll
        for (int off = 16; off; off >>= 1) g += __shfl_xor_sync(0xffffffffu, g, off);
        if (lane == 0) g_gate[(size_t)n * NKV + h] = 3.f / (1.f + __expf(-g));
    }
}

// ---------------- V: gate add + transpose + round ----------------------------
__global__ __launch_bounds__(256) void vtrans(const float* __restrict__ ve) {
    __shared__ float st[32 * 65];
    const int tid = threadIdx.x;
    const int t0  = blockIdx.x * 32;
    const int bkv = blockIdx.y;
    const int b   = bkv >> 2;
    const int kv  = bkv & 3;

#pragma unroll
    for (int l = 0; l < 2; l++) {
        int idx = tid + l * 256;
        int tt = idx >> 4, c4 = idx & 15;
        size_t n = (size_t)b * TT + t0 + tt;
        size_t base = n * (NKV * HD) + kv * HD + c4 * 4;
        float4 vr = *(const float4*)(g_vraw + base);
        float4 vv = *(const float4*)(ve + base);
        float  gg = g_gate[n * NKV + kv];
        st[tt * 65 + c4 * 4 + 0] = f2tff(vr.x + gg * vv.x);
        st[tt * 65 + c4 * 4 + 1] = f2tff(vr.y + gg * vv.y);
        st[tt * 65 + c4 * 4 + 2] = f2tff(vr.z + gg * vv.z);
        st[tt * 65 + c4 * 4 + 3] = f2tff(vr.w + gg * vv.w);
    }
    __syncthreads();
#pragma unroll
    for (int l = 0; l < 2; l++) {
        int idx = tid + l * 256;
        int d = idx >> 3, tc = idx & 7;
        float4 o = make_float4(st[(tc * 4 + 0) * 65 + d], st[(tc * 4 + 1) * 65 + d],
                               st[(tc * 4 + 2) * 65 + d], st[(tc * 4 + 3) * 65 + d]);
        *(float4*)(g_vt + ((size_t)bkv * HD + d) * TT + t0 + tc * 4) = o;
    }
}

// ---------------- tensor-core sliding-window flash attention -----------------
// grid (T/128, B*H), 128 threads = 4 warps; warp w owns q rows w*32..w*32+31.
// Non-full tiles restrict the j-group range [jlo,jhi] (warp-uniform branches).
#define AS 68
#define QT 128
#define KVSTG (64 * AS)
__global__ __launch_bounds__(128) void attn_tc(const float* __restrict__ q,
                                               const float* __restrict__ k,
                                               const float* __restrict__ v,   // [B,KV,D,T]
                                               const int* __restrict__ winp,
                                               float* __restrict__ y) {
    extern __shared__ float sm[];
    float* sQ = sm;
    float* sP = sm;
    float* sK = sm + QT * AS;
    float* sV = sK + 2 * KVSTG;

    const int tid  = threadIdx.x;
    const int lane = tid & 31;
    const int wid  = tid >> 5;
    const int g = lane >> 2, t = lane & 3;

    const int qt = blockIdx.x;
    const int bh = blockIdx.y;
    const int b  = bh >> 4;
    const int h  = bh & 15;
    const int kvh = h >> 2;
    const int q0  = qt * QT;
    const int win = winp[0];

    int kstart = q0 - win; if (kstart < 0) kstart = 0;
    const int kt0 = kstart >> 6;
    const int kt1 = (q0 + QT - 1) >> 6;

    const size_t kvbase = ((size_t)b * NKV + kvh) * TT;
    const size_t vtbase = ((size_t)b * NKV + kvh) * HD;

    const int ldsmB  = ((lane & 7) + ((lane >> 4) << 3)) * AS + ((lane >> 3) & 1) * 4;
    const int ldsmA0 = (wid * 32 + (lane & 15)) * AS + (lane >> 4) * 4;
    const int ldsmA1 = ldsmA0 + 16 * AS;

    {
        const int k0 = kt0 * 64;
#pragma unroll
        for (int l = 0; l < 8; l++) {
            int idx = tid + l * 128;
            int row = idx >> 4, c4 = idx & 15;
            cpa16(&sK[row * AS + c4 * 4], k + (kvbase + k0 + row) * HD + c4 * 4);
            cpa16(&sV[row * AS + c4 * 4], v + (vtbase + row) * TT + k0 + c4 * 4);
        }
        cp_commit();
    }

    {
        size_t qb = (((size_t)b * NH + h) * TT + q0) * HD;
#pragma unroll
        for (int l = 0; l < 16; l++) {
            int idx = tid + l * 128;
            int row = idx >> 4, c4 = idx & 15;
            *(float4*)&sQ[row * AS + c4 * 4] =
                *(const float4*)(q + qb + (size_t)row * HD + c4 * 4);
        }
    }
    __syncthreads();

    unsigned qa[2][8][4];
#pragma unroll
    for (int ks = 0; ks < 8; ks++) {
        ldsm4(qa[0][ks][0], qa[0][ks][1], qa[0][ks][2], qa[0][ks][3], sQ + ldsmA0 + ks * 8);
        ldsm4(qa[1][ks][0], qa[1][ks][1], qa[1][ks][2], qa[1][ks][3], sQ + ldsmA1 + ks * 8);
    }

    float accO[2][8][4];
#pragma unroll
    for (int rb = 0; rb < 2; rb++)
#pragma unroll
        for (int j = 0; j < 8; j++)
#pragma unroll
            for (int e = 0; e < 4; e++) accO[rb][j][e] = 0.f;
    float mrow[4] = {-1e30f, -1e30f, -1e30f, -1e30f};
    float lrow[4] = {0.f, 0.f, 0.f, 0.f};

    const int rw   = wid * 32 + g;
    const int rmin = q0 + wid * 32;
    const int rmax = rmin + 31;
    const int rr[4] = {q0 + rw, q0 + rw + 8, q0 + rw + 16, q0 + rw + 24};

    int stage = 0;
    for (int kt = kt0; kt <= kt1; kt++, stage ^= 1) {
        const int k0 = kt * 64;
        cp_wait<0>();
        __syncthreads();
        if (kt < kt1) {
            const int nk0 = (kt + 1) * 64;
            float* dK = sK + (stage ^ 1) * KVSTG;
            float* dV = sV + (stage ^ 1) * KVSTG;
#pragma unroll
            for (int l = 0; l < 8; l++) {
                int idx = tid + l * 128;
                int row = idx >> 4, c4 = idx & 15;
                cpa16(&dK[row * AS + c4 * 4], k + (kvbase + nk0 + row) * HD + c4 * 4);
                cpa16(&dV[row * AS + c4 * 4], v + (vtbase + row) * TT + nk0 + c4 * 4);
            }
            cp_commit();
        }
        if (k0 > rmax || k0 + 63 < rmin - win) continue;

        const float* cK = sK + stage * KVSTG;
        const float* cV = sV + stage * KVSTG;

        const bool full = (k0 + 63 <= rmin) && (rmax - k0 <= win);
        // warp-uniform j-group bounds: groups fully outside [rmin-win, rmax] skipped
        int jlo = 0, jhi = 7;
        if (!full) {
            int cmin = rmin - win - k0;           // cols < cmin invalid for all rows
            int cmax = rmax - k0;                 // cols > cmax invalid for all rows
            if (cmin > 0)  jlo = cmin >> 3;
            if (cmax < 63) jhi = cmax >> 3;
        }

        float s[2][8][4];
#pragma unroll
        for (int rb = 0; rb < 2; rb++)
#pragma unroll
            for (int j = 0; j < 8; j++)
#pragma unroll
                for (int e = 0; e < 4; e++) s[rb][j][e] = 0.f;
#pragma unroll
        for (int ks = 0; ks < 8; ks++) {
            const int kk = ks * 8;
            unsigned bb[8][2];
#pragma unroll
            for (int jp = 0; jp < 4; jp++) {
                if (2*jp+1 < jlo || 2*jp > jhi) continue;
                ldsm4(bb[2*jp][0], bb[2*jp][1], bb[2*jp+1][0], bb[2*jp+1][1],
                      cK + ldsmB + jp * 16 * AS + kk);
            }
#pragma unroll
            for (int rb = 0; rb < 2; rb++)
#pragma unroll
                for (int j = 0; j < 8; j++) {
                    if (j < jlo || j > jhi) continue;
                    mma_tf32(s[rb][j][0], s[rb][j][1], s[rb][j][2], s[rb][j][3],
                             qa[rb][ks][0], qa[rb][ks][1], qa[rb][ks][2], qa[rb][ks][3],
                             bb[j][0], bb[j][1]);
                }
        }

        if (!full) {
#pragma unroll
            for (int rb = 0; rb < 2; rb++)
#pragma unroll
                for (int j = 0; j < 8; j++) {
                    int c0 = k0 + j * 8 + 2 * t;
                    int da = rr[2*rb]   - c0;
                    int db = rr[2*rb+1] - c0;
                    if (!(da     >= 0 && da     <= win)) s[rb][j][0] = -1e30f;
                    if (!(da - 1 >= 0 && da - 1 <= win)) s[rb][j][1] = -1e30f;
                    if (!(db     >= 0 && db     <= win)) s[rb][j][2] = -1e30f;
                    if (!(db - 1 >= 0 && db - 1 <= win)) s[rb][j][3] = -1e30f;
                }
        }

        float mt[4] = {-1e30f, -1e30f, -1e30f, -1e30f};
#pragma unroll
        for (int rb = 0; rb < 2; rb++)
#pragma unroll
            for (int j = 0; j < 8; j++) {
                mt[2*rb]   = fmaxf(mt[2*rb],   fmaxf(s[rb][j][0], s[rb][j][1]));
                mt[2*rb+1] = fmaxf(mt[2*rb+1], fmaxf(s[rb][j][2], s[rb][j][3]));
            }
#pragma unroll
        for (int r = 0; r < 4; r++) {
            mt[r] = fmaxf(mt[r], __shfl_xor_sync(0xffffffffu, mt[r], 1));
            mt[r] = fmaxf(mt[r], __shfl_xor_sync(0xffffffffu, mt[r], 2));
        }
        float mn[4], al[4], rs[4];
#pragma unroll
        for (int r = 0; r < 4; r++) {
            mn[r] = fmaxf(mrow[r], mt[r]);
            al[r] = exp2f(mrow[r] - mn[r]);
            rs[r] = 0.f;
        }
#pragma unroll
        for (int rb = 0; rb < 2; rb++)
#pragma unroll
            for (int j = 0; j < 8; j++) {
                if (j < jlo || j > jhi) continue;   // skipped groups: p==0, PV skipped too
                float p0 = exp2f(s[rb][j][0] - mn[2*rb]);
                float p1 = exp2f(s[rb][j][1] - mn[2*rb]);
                float p2 = exp2f(s[rb][j][2] - mn[2*rb+1]);
                float p3 = exp2f(s[rb][j][3] - mn[2*rb+1]);
                rs[2*rb]   += p0 + p1;
                rs[2*rb+1] += p2 + p3;
                int cb = j * 8 + 2 * t;
                int rbase = rw + rb * 16;
                *(float2*)&sP[rbase * AS + cb]       = make_float2(f2tff(p0), f2tff(p1));
                *(float2*)&sP[(rbase + 8) * AS + cb] = make_float2(f2tff(p2), f2tff(p3));
            }
#pragma unroll
        for (int r = 0; r < 4; r++) {
            rs[r] += __shfl_xor_sync(0xffffffffu, rs[r], 1);
            rs[r] += __shfl_xor_sync(0xffffffffu, rs[r], 2);
            lrow[r] = lrow[r] * al[r] + rs[r];
            mrow[r] = mn[r];
        }
#pragma unroll
        for (int rb = 0; rb < 2; rb++)
#pragma unroll
            for (int j = 0; j < 8; j++) {
                accO[rb][j][0] *= al[2*rb];   accO[rb][j][1] *= al[2*rb];
                accO[rb][j][2] *= al[2*rb+1]; accO[rb][j][3] *= al[2*rb+1];
            }
        __syncwarp();

#pragma unroll
        for (int ks = 0; ks < 8; ks++) {
            if (ks < jlo || ks > jhi) continue;     // P cols of this ks-group are all zero
            const int kk = ks * 8;
            unsigned pa[2][4];
            ldsm4(pa[0][0], pa[0][1], pa[0][2], pa[0][3], sP + ldsmA0 + kk);
            ldsm4(pa[1][0], pa[1][1], pa[1][2], pa[1][3], sP + ldsmA1 + kk);
            unsigned bb[8][2];
#pragma unroll
            for (int jp = 0; jp < 4; jp++)
                ldsm4(bb[2*jp][0], bb[2*jp][1], bb[2*jp+1][0], bb[2*jp+1][1],
                      cV + ldsmB + jp * 16 * AS + kk);
#pragma unroll
            for (int rb = 0; rb < 2; rb++)
#pragma unroll
                for (int j = 0; j < 8; j++)
                    mma_tf32(accO[rb][j][0], accO[rb][j][1], accO[rb][j][2], accO[rb][j][3],
                             pa[rb][0], pa[rb][1], pa[rb][2], pa[rb][3],
                             bb[j][0], bb[j][1]);
        }
    }

    float il[4];
#pragma unroll
    for (int r = 0; r < 4; r++) il[r] = 1.0f / lrow[r];
#pragma unroll
    for (int rb = 0; rb < 2; rb++)
#pragma unroll
        for (int j = 0; j < 8; j++) {
            int d = h * HD + j * 8 + 2 * t;
            *(float2*)(y + ((size_t)b * TT + rr[2*rb]) * CC + d) =
                make_float2(f2tff(accO[rb][j][0] * il[2*rb]),
                            f2tff(accO[rb][j][1] * il[2*rb]));
            *(float2*)(y + ((size_t)b * TT + rr[2*rb+1]) * CC + d) =
                make_float2(f2tff(accO[rb][j][2] * il[2*rb+1]),
                            f2tff(accO[rb][j][3] * il[2*rb+1]));
        }
}

// ---------------- launcher ---------------------------------------------------
extern "C" void kernel_launch(void* const* d_in, const int* in_sizes, int n_in,
                              void* d_out, int out_size) {
    const float* x    = (const float*)d_in[0];
    const float* ve   = (const float*)d_in[1];
    const float* cosp = (const float*)d_in[2];
    const float* sinp = (const float*)d_in[3];
    const float* wq   = (const float*)d_in[4];
    const float* wk   = (const float*)d_in[5];
    const float* wv   = (const float*)d_in[6];
    const float* wo   = (const float*)d_in[7];
    const float* wg   = (const float*)d_in[8];
    const int*   win  = (const int*)d_in[9];
    float* out = (float*)d_out;

    float *qn, *kn, *vt, *att, *wor;
    cudaGetSymbolAddress((void**)&qn,  g_qn);
    cudaGetSymbolAddress((void**)&kn,  g_kn);
    cudaGetSymbolAddress((void**)&vt,  g_vt);
    cudaGetSymbolAddress((void**)&att, g_att);
    cudaGetSymbolAddress((void**)&wor, g_wor);

    cvt_all<<<2368, 256>>>((const float4*)x, (const float4*)wq, (const float4*)wk,
                           (const float4*)wv, (const float4*)wo);

    int gsmem = 6 * GSTG * (int)sizeof(float);  // 110592 B
    cudaFuncSetAttribute(gemm_qkv,  cudaFuncAttributeMaxDynamicSharedMemorySize, gsmem);
    cudaFuncSetAttribute(gemm_tf32, cudaFuncAttributeMaxDynamicSharedMemorySize, gsmem);

    gemm_qkv<<<768, 128, gsmem>>>();

    postproc<<<NTOK, 256>>>(x, cosp, sinp, wg);

    vtrans<<<dim3(TT / 32, BB * NKV), 256>>>(ve);

    int smem = (QT * AS + 4 * KVSTG) * (int)sizeof(float);  // 104448 B
    cudaFuncSetAttribute(attn_tc, cudaFuncAttributeMaxDynamicSharedMemorySize, smem);
    attn_tc<<<dim3(TT / QT, BB * NH), 128, smem>>>(qn, kn, vt, win, att);

    gemm_tf32<<<dim3(CC / 128, NTOK / 128), 128, gsmem>>>(att, wor, out, CC, CC);
}

// round 15
// speedup vs baseline: 1.2057x; 1.2057x over previous
#include <cuda_runtime.h>
#include <math.h>

#define BB   4
#define TT   2048
#define CC   1024
#define NH   16
#define NKV  4
#define HD   64
#define NTOK (BB*TT)
#define GATE_CH 12

// ---------------- scratch ----------------------------------------------------
__device__ float g_qraw[NTOK*CC];
__device__ float g_kraw[NTOK*NKV*HD];
__device__ float g_vraw[NTOK*NKV*HD];
__device__ float g_gate[NTOK*NKV];
__device__ float g_qn[NTOK*CC];          // [B,H,T,D] tf32, scale*log2e folded
__device__ float g_kn[NTOK*NKV*HD];      // [B,KV,T,D] tf32
__device__ float g_vt[NTOK*NKV*HD];      // [B,KV,D,T] tf32
__device__ float g_att[NTOK*CC];         // [B,T,H*D] tf32
__device__ float g_xr[NTOK*CC];
__device__ float g_wqr[CC*CC];
__device__ float g_wkr[NKV*HD*CC];
__device__ float g_wvr[NKV*HD*CC];
__device__ float g_wor[CC*CC];

// ---------------- helpers ----------------------------------------------------
__device__ __forceinline__ unsigned f2tf(float f) {
    unsigned u;
    asm("cvt.rna.tf32.f32 %0, %1;" : "=r"(u) : "f"(f));
    return u;
}
__device__ __forceinline__ float f2tff(float f) { return __uint_as_float(f2tf(f)); }
__device__ __forceinline__ void mma_tf32(float& d0, float& d1, float& d2, float& d3,
                                         unsigned a0, unsigned a1, unsigned a2, unsigned a3,
                                         unsigned b0, unsigned b1) {
    asm volatile(
        "mma.sync.aligned.m16n8k8.row.col.f32.tf32.tf32.f32 "
        "{%0,%1,%2,%3}, {%4,%5,%6,%7}, {%8,%9}, {%0,%1,%2,%3};"
        : "+f"(d0), "+f"(d1), "+f"(d2), "+f"(d3)
        : "r"(a0), "r"(a1), "r"(a2), "r"(a3), "r"(b0), "r"(b1));
}
__device__ __forceinline__ void ldsm4(unsigned& r0, unsigned& r1, unsigned& r2, unsigned& r3,
                                      const float* p) {
    unsigned a = (unsigned)__cvta_generic_to_shared(p);
    asm volatile("ldmatrix.sync.aligned.m8n8.x4.shared.b16 {%0,%1,%2,%3}, [%4];"
                 : "=r"(r0), "=r"(r1), "=r"(r2), "=r"(r3) : "r"(a));
}
__device__ __forceinline__ void cpa16(float* s, const float* g) {
    unsigned sa = (unsigned)__cvta_generic_to_shared(s);
    asm volatile("cp.async.cg.shared.global [%0], [%1], 16;" :: "r"(sa), "l"(g));
}
__device__ __forceinline__ void cp_commit() { asm volatile("cp.async.commit_group;"); }
template<int N> __device__ __forceinline__ void cp_wait() {
    asm volatile("cp.async.wait_group %0;" :: "n"(N));
}

// ---------------- one-shot tf32 rounding of all GEMM inputs ------------------
#define N4_X  (NTOK*CC/4)
#define N4_WQ (CC*CC/4)
#define N4_WK (NKV*HD*CC/4)
__global__ void cvt_all(const float4* __restrict__ x,  const float4* __restrict__ wq,
                        const float4* __restrict__ wk, const float4* __restrict__ wv,
                        const float4* __restrict__ wo) {
    const int total = N4_X + 2 * N4_WQ + 2 * N4_WK;
    int i = blockIdx.x * blockDim.x + threadIdx.x;
    const int str = gridDim.x * blockDim.x;
    for (; i < total; i += str) {
        const float4* s; float4* d; int off = i;
        if (off < N4_X) { s = x; d = (float4*)g_xr; }
        else if ((off -= N4_X) < N4_WQ) { s = wq; d = (float4*)g_wqr; }
        else if ((off -= N4_WQ) < N4_WK) { s = wk; d = (float4*)g_wkr; }
        else if ((off -= N4_WK) < N4_WK) { s = wv; d = (float4*)g_wvr; }
        else { off -= N4_WK; s = wo; d = (float4*)g_wor; }
        float4 v = s[off];
        d[off] = make_float4(f2tff(v.x), f2tff(v.y), f2tff(v.z), f2tff(v.w));
    }
}

// ---------------- tf32 NT GEMM body (3-stage cp.async, 4 warps) --------------
// block 128x128, BK=32, 128 threads = 4 warps (2m x 2n), warp tile 64x64.
#define GS 36
#define GSTG (128*GS)
__device__ __forceinline__ void gemm_body(const float* __restrict__ A,
                                          const float* __restrict__ W,
                                          float* __restrict__ out,
                                          int N, int K, int m0, int n0) {
    extern __shared__ float gsm[];
    float* smA = gsm;
    float* smB = gsm + 3 * GSTG;

    const int tid  = threadIdx.x;       // 0..127
    const int lane = tid & 31;
    const int wid  = tid >> 5;          // 0..3
    const int wm = (wid >> 1) * 64, wn = (wid & 1) * 64;
    const int g = lane >> 2, t = lane & 3;

    const int aoff = (wm + (lane & 15)) * GS + (lane >> 4) * 4;
    const int boff = (wn + (lane & 7) + ((lane >> 4) << 3)) * GS + ((lane >> 3) & 1) * 4;

    float acc[4][8][4];
#pragma unroll
    for (int i = 0; i < 4; i++)
#pragma unroll
        for (int j = 0; j < 8; j++)
#pragma unroll
            for (int e = 0; e < 4; e++) acc[i][j][e] = 0.f;

    const int nt = K / 32;
#pragma unroll
    for (int p = 0; p < 2; p++) {
        int k0 = p * 32;
#pragma unroll
        for (int l = 0; l < 8; l++) {
            int idx = tid + l * 128;
            int row = idx >> 3, c = idx & 7;
            cpa16(&smA[p * GSTG + row * GS + c * 4], A + (size_t)(m0 + row) * K + k0 + c * 4);
            cpa16(&smB[p * GSTG + row * GS + c * 4], W + (size_t)(n0 + row) * K + k0 + c * 4);
        }
        cp_commit();
    }
    cp_wait<1>();
    __syncthreads();

    int s = 0;
    for (int i = 0; i < nt; i++) {
        if (i + 2 < nt) {
            int k0 = (i + 2) * 32;
            int sn = (s + 2) % 3;
#pragma unroll
            for (int l = 0; l < 8; l++) {
                int idx = tid + l * 128;
                int row = idx >> 3, c = idx & 7;
                cpa16(&smA[sn * GSTG + row * GS + c * 4], A + (size_t)(m0 + row) * K + k0 + c * 4);
                cpa16(&smB[sn * GSTG + row * GS + c * 4], W + (size_t)(n0 + row) * K + k0 + c * 4);
            }
            cp_commit();
        }
        const float* pA = smA + s * GSTG + aoff;
        const float* pB = smB + s * GSTG + boff;
#pragma unroll
        for (int ks = 0; ks < 4; ks++) {
            const int kk = ks * 8;
            unsigned a[4][4];
#pragma unroll
            for (int ii = 0; ii < 4; ii++)
                ldsm4(a[ii][0], a[ii][1], a[ii][2], a[ii][3], pA + ii * 16 * GS + kk);
            unsigned b[8][2];
#pragma unroll
            for (int jp = 0; jp < 4; jp++)
                ldsm4(b[2*jp][0], b[2*jp][1], b[2*jp+1][0], b[2*jp+1][1],
                      pB + jp * 16 * GS + kk);
#pragma unroll
            for (int ii = 0; ii < 4; ii++)
#pragma unroll
                for (int j = 0; j < 8; j++)
                    mma_tf32(acc[ii][j][0], acc[ii][j][1], acc[ii][j][2], acc[ii][j][3],
                             a[ii][0], a[ii][1], a[ii][2], a[ii][3], b[j][0], b[j][1]);
        }
        if (i + 2 < nt) cp_wait<1>(); else cp_wait<0>();
        __syncthreads();
        s = (s + 1) % 3;
    }
#pragma unroll
    for (int i = 0; i < 4; i++) {
        int r = m0 + wm + i * 16 + g;
#pragma unroll
        for (int j = 0; j < 8; j++) {
            int c = n0 + wn + j * 8 + 2 * t;
            *(float2*)(out + (size_t)r * N + c) = make_float2(acc[i][j][0], acc[i][j][1]);
            *(float2*)(out + (size_t)(r + 8) * N + c) = make_float2(acc[i][j][2], acc[i][j][3]);
        }
    }
}

__global__ __launch_bounds__(128) void gemm_qkv() {
    const int bid = blockIdx.x;
    if (bid < 512) {
        gemm_body(g_xr, g_wqr, g_qraw, CC, CC, (bid >> 3) * 128, (bid & 7) * 128);
    } else {
        const int r = bid - 512;
        const bool isv = (r & 3) >= 2;
        gemm_body(g_xr, isv ? g_wvr : g_wkr, isv ? g_vraw : g_kraw,
                  NKV * HD, CC, (r >> 2) * 128, (r & 1) * 128);
    }
}

__global__ __launch_bounds__(128) void gemm_tf32(const float* __restrict__ A,
                                                 const float* __restrict__ W,
                                                 float* __restrict__ out,
                                                 int N, int K) {
    gemm_body(A, W, out, N, K, blockIdx.y * 128, blockIdx.x * 128);
}

// ---------------- rotary + rmsnorm + gate ------------------------------------
__device__ __forceinline__ void rope_norm(const float* __restrict__ in,
                                          float* __restrict__ outp,
                                          int t, int lane, float mult,
                                          const float* __restrict__ cosp,
                                          const float* __restrict__ sinp) {
    float x1 = in[lane];
    float x2 = in[32 + lane];
    float c  = cosp[t * 32 + lane];
    float s  = sinp[t * 32 + lane];
    float o1 =  x1 * c + x2 * s;
    float o2 = -x1 * s + x2 * c;
    float ss = o1 * o1 + o2 * o2;
#pragma unroll
    for (int off = 16; off; off >>= 1) ss += __shfl_xor_sync(0xffffffffu, ss, off);
    float r = rsqrtf(ss * (1.0f / HD) + 1e-6f) * mult;
    outp[lane]      = f2tff(o1 * r);
    outp[32 + lane] = f2tff(o2 * r);
}

__global__ __launch_bounds__(256) void postproc(const float* __restrict__ x,
                                                const float* __restrict__ cosp,
                                                const float* __restrict__ sinp,
                                                const float* __restrict__ wgate) {
    const int n = blockIdx.x;
    const int b = n / TT;
    const int t = n % TT;
    const int w    = threadIdx.x >> 5;
    const int lane = threadIdx.x & 31;

    const float QMULT = 1.15f * 0.125f * 1.4426950408889634f;
#pragma unroll
    for (int h = w; h < NH; h += 8) {
        size_t obase = (((size_t)b * NH + h) * TT + t) * HD;
        rope_norm(g_qraw + (size_t)n * CC + h * HD, g_qn + obase, t, lane, QMULT, cosp, sinp);
    }
    if (w < 4) {
        int h = w;
        size_t obase = (((size_t)b * NKV + h) * TT + t) * HD;
        rope_norm(g_kraw + (size_t)n * NKV * HD + h * HD, g_kn + obase, t, lane,
                  1.15f, cosp, sinp);
    } else {
        int h = w - 4;
        float g = (lane < GATE_CH)
                    ? x[(size_t)n * CC + lane] * wgate[h * GATE_CH + lane] : 0.f;
#pragma unroll
        for (int off = 16; off; off >>= 1) g += __shfl_xor_sync(0xffffffffu, g, off);
        if (lane == 0) g_gate[(size_t)n * NKV + h] = 3.f / (1.f + __expf(-g));
    }
}

// ---------------- V: gate add + transpose + round ----------------------------
__global__ __launch_bounds__(256) void vtrans(const float* __restrict__ ve) {
    __shared__ float st[32 * 65];
    const int tid = threadIdx.x;
    const int t0  = blockIdx.x * 32;
    const int bkv = blockIdx.y;
    const int b   = bkv >> 2;
    const int kv  = bkv & 3;

#pragma unroll
    for (int l = 0; l < 2; l++) {
        int idx = tid + l * 256;
        int tt = idx >> 4, c4 = idx & 15;
        size_t n = (size_t)b * TT + t0 + tt;
        size_t base = n * (NKV * HD) + kv * HD + c4 * 4;
        float4 vr = *(const float4*)(g_vraw + base);
        float4 vv = *(const float4*)(ve + base);
        float  gg = g_gate[n * NKV + kv];
        st[tt * 65 + c4 * 4 + 0] = f2tff(vr.x + gg * vv.x);
        st[tt * 65 + c4 * 4 + 1] = f2tff(vr.y + gg * vv.y);
        st[tt * 65 + c4 * 4 + 2] = f2tff(vr.z + gg * vv.z);
        st[tt * 65 + c4 * 4 + 3] = f2tff(vr.w + gg * vv.w);
    }
    __syncthreads();
#pragma unroll
    for (int l = 0; l < 2; l++) {
        int idx = tid + l * 256;
        int d = idx >> 3, tc = idx & 7;
        float4 o = make_float4(st[(tc * 4 + 0) * 65 + d], st[(tc * 4 + 1) * 65 + d],
                               st[(tc * 4 + 2) * 65 + d], st[(tc * 4 + 3) * 65 + d]);
        *(float4*)(g_vt + ((size_t)bkv * HD + d) * TT + t0 + tc * 4) = o;
    }
}

// ---------------- tensor-core sliding-window flash attention -----------------
// grid (T/128, B*H), 128 threads = 4 warps; warp w owns q rows w*32..w*32+31.
#define AS 68
#define QT 128
#define KVSTG (64 * AS)
__global__ __launch_bounds__(128) void attn_tc(const float* __restrict__ q,
                                               const float* __restrict__ k,
                                               const float* __restrict__ v,   // [B,KV,D,T]
                                               const int* __restrict__ winp,
                                               float* __restrict__ y) {
    extern __shared__ float sm[];
    float* sQ = sm;
    float* sP = sm;
    float* sK = sm + QT * AS;
    float* sV = sK + 2 * KVSTG;

    const int tid  = threadIdx.x;
    const int lane = tid & 31;
    const int wid  = tid >> 5;
    const int g = lane >> 2, t = lane & 3;

    const int qt = blockIdx.x;
    const int bh = blockIdx.y;
    const int b  = bh >> 4;
    const int h  = bh & 15;
    const int kvh = h >> 2;
    const int q0  = qt * QT;
    const int win = winp[0];

    int kstart = q0 - win; if (kstart < 0) kstart = 0;
    const int kt0 = kstart >> 6;
    const int kt1 = (q0 + QT - 1) >> 6;

    const size_t kvbase = ((size_t)b * NKV + kvh) * TT;
    const size_t vtbase = ((size_t)b * NKV + kvh) * HD;

    const int ldsmB  = ((lane & 7) + ((lane >> 4) << 3)) * AS + ((lane >> 3) & 1) * 4;
    const int ldsmA0 = (wid * 32 + (lane & 15)) * AS + (lane >> 4) * 4;
    const int ldsmA1 = ldsmA0 + 16 * AS;

    {
        const int k0 = kt0 * 64;
#pragma unroll
        for (int l = 0; l < 8; l++) {
            int idx = tid + l * 128;
            int row = idx >> 4, c4 = idx & 15;
            cpa16(&sK[row * AS + c4 * 4], k + (kvbase + k0 + row) * HD + c4 * 4);
            cpa16(&sV[row * AS + c4 * 4], v + (vtbase + row) * TT + k0 + c4 * 4);
        }
        cp_commit();
    }

    {
        size_t qb = (((size_t)b * NH + h) * TT + q0) * HD;
#pragma unroll
        for (int l = 0; l < 16; l++) {
            int idx = tid + l * 128;
            int row = idx >> 4, c4 = idx & 15;
            *(float4*)&sQ[row * AS + c4 * 4] =
                *(const float4*)(q + qb + (size_t)row * HD + c4 * 4);
        }
    }
    __syncthreads();

    unsigned qa[2][8][4];
#pragma unroll
    for (int ks = 0; ks < 8; ks++) {
        ldsm4(qa[0][ks][0], qa[0][ks][1], qa[0][ks][2], qa[0][ks][3], sQ + ldsmA0 + ks * 8);
        ldsm4(qa[1][ks][0], qa[1][ks][1], qa[1][ks][2], qa[1][ks][3], sQ + ldsmA1 + ks * 8);
    }

    float accO[2][8][4];
#pragma unroll
    for (int rb = 0; rb < 2; rb++)
#pragma unroll
        for (int j = 0; j < 8; j++)
#pragma unroll
            for (int e = 0; e < 4; e++) accO[rb][j][e] = 0.f;
    float mrow[4] = {-1e30f, -1e30f, -1e30f, -1e30f};
    float lrow[4] = {0.f, 0.f, 0.f, 0.f};

    const int rw   = wid * 32 + g;
    const int rmin = q0 + wid * 32;
    const int rmax = rmin + 31;
    const int rr[4] = {q0 + rw, q0 + rw + 8, q0 + rw + 16, q0 + rw + 24};

    int stage = 0;
    for (int kt = kt0; kt <= kt1; kt++, stage ^= 1) {
        const int k0 = kt * 64;
        cp_wait<0>();
        __syncthreads();
        if (kt < kt1) {
            const int nk0 = (kt + 1) * 64;
            float* dK = sK + (stage ^ 1) * KVSTG;
            float* dV = sV + (stage ^ 1) * KVSTG;
#pragma unroll
            for (int l = 0; l < 8; l++) {
                int idx = tid + l * 128;
                int row = idx >> 4, c4 = idx & 15;
                cpa16(&dK[row * AS + c4 * 4], k + (kvbase + nk0 + row) * HD + c4 * 4);
                cpa16(&dV[row * AS + c4 * 4], v + (vtbase + row) * TT + nk0 + c4 * 4);
            }
            cp_commit();
        }
        if (k0 > rmax || k0 + 63 < rmin - win) continue;

        const float* cK = sK + stage * KVSTG;
        const float* cV = sV + stage * KVSTG;

        float s[2][8][4];
#pragma unroll
        for (int rb = 0; rb < 2; rb++)
#pragma unroll
            for (int j = 0; j < 8; j++)
#pragma unroll
                for (int e = 0; e < 4; e++) s[rb][j][e] = 0.f;
#pragma unroll
        for (int ks = 0; ks < 8; ks++) {
            const int kk = ks * 8;
            unsigned bb[8][2];
#pragma unroll
            for (int jp = 0; jp < 4; jp++)
                ldsm4(bb[2*jp][0], bb[2*jp][1], bb[2*jp+1][0], bb[2*jp+1][1],
                      cK + ldsmB + jp * 16 * AS + kk);
#pragma unroll
            for (int rb = 0; rb < 2; rb++)
#pragma unroll
                for (int j = 0; j < 8; j++)
                    mma_tf32(s[rb][j][0], s[rb][j][1], s[rb][j][2], s[rb][j][3],
                             qa[rb][ks][0], qa[rb][ks][1], qa[rb][ks][2], qa[rb][ks][3],
                             bb[j][0], bb[j][1]);
        }

        bool full = (k0 + 63 <= rmin) && (rmax - k0 <= win);
        if (!full) {
#pragma unroll
            for (int rb = 0; rb < 2; rb++)
#pragma unroll
                for (int j = 0; j < 8; j++) {
                    int c0 = k0 + j * 8 + 2 * t;
                    int da = rr[2*rb]   - c0;
                    int db = rr[2*rb+1] - c0;
                    if (!(da     >= 0 && da     <= win)) s[rb][j][0] = -1e30f;
                    if (!(da - 1 >= 0 && da - 1 <= win)) s[rb][j][1] = -1e30f;
                    if (!(db     >= 0 && db     <= win)) s[rb][j][2] = -1e30f;
                    if (!(db - 1 >= 0 && db - 1 <= win)) s[rb][j][3] = -1e30f;
                }
        }

        float mt[4] = {-1e30f, -1e30f, -1e30f, -1e30f};
#pragma unroll
        for (int rb = 0; rb < 2; rb++)
#pragma unroll
            for (int j = 0; j < 8; j++) {
                mt[2*rb]   = fmaxf(mt[2*rb],   fmaxf(s[rb][j][0], s[rb][j][1]));
                mt[2*rb+1] = fmaxf(mt[2*rb+1], fmaxf(s[rb][j][2], s[rb][j][3]));
            }
#pragma unroll
        for (int r = 0; r < 4; r++) {
            mt[r] = fmaxf(mt[r], __shfl_xor_sync(0xffffffffu, mt[r], 1));
            mt[r] = fmaxf(mt[r], __shfl_xor_sync(0xffffffffu, mt[r], 2));
        }
        float mn[4], al[4], rs[4];
#pragma unroll
        for (int r = 0; r < 4; r++) {
            mn[r] = fmaxf(mrow[r], mt[r]);
            al[r] = exp2f(mrow[r] - mn[r]);
            rs[r] = 0.f;
        }
#pragma unroll
        for (int rb = 0; rb < 2; rb++)
#pragma unroll
            for (int j = 0; j < 8; j++) {
                float p0 = exp2f(s[rb][j][0] - mn[2*rb]);
                float p1 = exp2f(s[rb][j][1] - mn[2*rb]);
                float p2 = exp2f(s[rb][j][2] - mn[2*rb+1]);
                float p3 = exp2f(s[rb][j][3] - mn[2*rb+1]);
                rs[2*rb]   += p0 + p1;
                rs[2*rb+1] += p2 + p3;
                int cb = j * 8 + 2 * t;
                int rbase = rw + rb * 16;
                *(float2*)&sP[rbase * AS + cb]       = make_float2(f2tff(p0), f2tff(p1));
                *(float2*)&sP[(rbase + 8) * AS + cb] = make_float2(f2tff(p2), f2tff(p3));
            }
#pragma unroll
        for (int r = 0; r < 4; r++) {
            rs[r] += __shfl_xor_sync(0xffffffffu, rs[r], 1);
            rs[r] += __shfl_xor_sync(0xffffffffu, rs[r], 2);
            lrow[r] = lrow[r] * al[r] + rs[r];
            mrow[r] = mn[r];
        }
#pragma unroll
        for (int rb = 0; rb < 2; rb++)
#pragma unroll
            for (int j = 0; j < 8; j++) {
                accO[rb][j][0] *= al[2*rb];   accO[rb][j][1] *= al[2*rb];
                accO[rb][j][2] *= al[2*rb+1]; accO[rb][j][3] *= al[2*rb+1];
            }
        __syncwarp();

#pragma unroll
        for (int ks = 0; ks < 8; ks++) {
            const int kk = ks * 8;
            unsigned pa[2][4];
            ldsm4(pa[0][0], pa[0][1], pa[0][2], pa[0][3], sP + ldsmA0 + kk);
            ldsm4(pa[1][0], pa[1][1], pa[1][2], pa[1][3], sP + ldsmA1 + kk);
            unsigned bb[8][2];
#pragma unroll
            for (int jp = 0; jp < 4; jp++)
                ldsm4(bb[2*jp][0], bb[2*jp][1], bb[2*jp+1][0], bb[2*jp+1][1],
                      cV + ldsmB + jp * 16 * AS + kk);
#pragma unroll
            for (int rb = 0; rb < 2; rb++)
#pragma unroll
                for (int j = 0; j < 8; j++)
                    mma_tf32(accO[rb][j][0], accO[rb][j][1], accO[rb][j][2], accO[rb][j][3],
                             pa[rb][0], pa[rb][1], pa[rb][2], pa[rb][3],
                             bb[j][0], bb[j][1]);
        }
    }

    float il[4];
#pragma unroll
    for (int r = 0; r < 4; r++) il[r] = 1.0f / lrow[r];
#pragma unroll
    for (int rb = 0; rb < 2; rb++)
#pragma unroll
        for (int j = 0; j < 8; j++) {
            int d = h * HD + j * 8 + 2 * t;
            *(float2*)(y + ((size_t)b * TT + rr[2*rb]) * CC + d) =
                make_float2(f2tff(accO[rb][j][0] * il[2*rb]),
                            f2tff(accO[rb][j][1] * il[2*rb]));
            *(float2*)(y + ((size_t)b * TT + rr[2*rb+1]) * CC + d) =
                make_float2(f2tff(accO[rb][j][2] * il[2*rb+1]),
                            f2tff(accO[rb][j][3] * il[2*rb+1]));
        }
}

// ---------------- launcher ---------------------------------------------------
extern "C" void kernel_launch(void* const* d_in, const int* in_sizes, int n_in,
                              void* d_out, int out_size) {
    const float* x    = (const float*)d_in[0];
    const float* ve   = (const float*)d_in[1];
    const float* cosp = (const float*)d_in[2];
    const float* sinp = (const float*)d_in[3];
    const float* wq   = (const float*)d_in[4];
    const float* wk   = (const float*)d_in[5];
    const float* wv   = (const float*)d_in[6];
    const float* wo   = (const float*)d_in[7];
    const float* wg   = (const float*)d_in[8];
    const int*   win  = (const int*)d_in[9];
    float* out = (float*)d_out;

    float *qn, *kn, *vt, *att, *wor;
    cudaGetSymbolAddress((void**)&qn,  g_qn);
    cudaGetSymbolAddress((void**)&kn,  g_kn);
    cudaGetSymbolAddress((void**)&vt,  g_vt);
    cudaGetSymbolAddress((void**)&att, g_att);
    cudaGetSymbolAddress((void**)&wor, g_wor);

    cvt_all<<<2368, 256>>>((const float4*)x, (const float4*)wq, (const float4*)wk,
                           (const float4*)wv, (const float4*)wo);

    int gsmem = 6 * GSTG * (int)sizeof(float);  // 110592 B
    cudaFuncSetAttribute(gemm_qkv,  cudaFuncAttributeMaxDynamicSharedMemorySize, gsmem);
    cudaFuncSetAttribute(gemm_tf32, cudaFuncAttributeMaxDynamicSharedMemorySize, gsmem);

    gemm_qkv<<<768, 128, gsmem>>>();

    postproc<<<NTOK, 256>>>(x, cosp, sinp, wg);

    vtrans<<<dim3(TT / 32, BB * NKV), 256>>>(ve);

    int smem = (QT * AS + 4 * KVSTG) * (int)sizeof(float);  // 104448 B
    cudaFuncSetAttribute(attn_tc, cudaFuncAttributeMaxDynamicSharedMemorySize, smem);
    attn_tc<<<dim3(TT / QT, BB * NH), 128, smem>>>(qn, kn, vt, win, att);

    gemm_tf32<<<dim3(CC / 128, NTOK / 128), 128, gsmem>>>(att, wor, out, CC, CC);
}

// round 16
// speedup vs baseline: 1.2104x; 1.0038x over previous
#include <cuda_runtime.h>
#include <math.h>

#define BB   4
#define TT   2048
#define CC   1024
#define NH   16
#define NKV  4
#define HD   64
#define NTOK (BB*TT)
#define GATE_CH 12

// ---------------- scratch ----------------------------------------------------
__device__ float g_qraw[NTOK*CC];
__device__ float g_kraw[NTOK*NKV*HD];
__device__ float g_vraw[NTOK*NKV*HD];
__device__ float g_qn[NTOK*CC];          // [B,H,T,D] tf32, scale*log2e folded
__device__ float g_kn[NTOK*NKV*HD];      // [B,KV,T,D] tf32
__device__ float g_vt[NTOK*NKV*HD];      // [B,KV,D,T] tf32
__device__ float g_att[NTOK*CC];         // [B,T,H*D] tf32
__device__ float g_xr[NTOK*CC];
__device__ float g_wqr[CC*CC];
__device__ float g_wkr[NKV*HD*CC];
__device__ float g_wvr[NKV*HD*CC];
__device__ float g_wor[CC*CC];

// ---------------- helpers ----------------------------------------------------
__device__ __forceinline__ unsigned f2tf(float f) {
    unsigned u;
    asm("cvt.rna.tf32.f32 %0, %1;" : "=r"(u) : "f"(f));
    return u;
}
__device__ __forceinline__ float f2tff(float f) { return __uint_as_float(f2tf(f)); }
__device__ __forceinline__ void mma_tf32(float& d0, float& d1, float& d2, float& d3,
                                         unsigned a0, unsigned a1, unsigned a2, unsigned a3,
                                         unsigned b0, unsigned b1) {
    asm volatile(
        "mma.sync.aligned.m16n8k8.row.col.f32.tf32.tf32.f32 "
        "{%0,%1,%2,%3}, {%4,%5,%6,%7}, {%8,%9}, {%0,%1,%2,%3};"
        : "+f"(d0), "+f"(d1), "+f"(d2), "+f"(d3)
        : "r"(a0), "r"(a1), "r"(a2), "r"(a3), "r"(b0), "r"(b1));
}
__device__ __forceinline__ void ldsm4(unsigned& r0, unsigned& r1, unsigned& r2, unsigned& r3,
                                      const float* p) {
    unsigned a = (unsigned)__cvta_generic_to_shared(p);
    asm volatile("ldmatrix.sync.aligned.m8n8.x4.shared.b16 {%0,%1,%2,%3}, [%4];"
                 : "=r"(r0), "=r"(r1), "=r"(r2), "=r"(r3) : "r"(a));
}
__device__ __forceinline__ void cpa16(float* s, const float* g) {
    unsigned sa = (unsigned)__cvta_generic_to_shared(s);
    asm volatile("cp.async.cg.shared.global [%0], [%1], 16;" :: "r"(sa), "l"(g));
}
__device__ __forceinline__ void cp_commit() { asm volatile("cp.async.commit_group;"); }
template<int N> __device__ __forceinline__ void cp_wait() {
    asm volatile("cp.async.wait_group %0;" :: "n"(N));
}

// ---------------- one-shot tf32 rounding of all GEMM inputs ------------------
#define N4_X  (NTOK*CC/4)
#define N4_WQ (CC*CC/4)
#define N4_WK (NKV*HD*CC/4)
__global__ void cvt_all(const float4* __restrict__ x,  const float4* __restrict__ wq,
                        const float4* __restrict__ wk, const float4* __restrict__ wv,
                        const float4* __restrict__ wo) {
    const int total = N4_X + 2 * N4_WQ + 2 * N4_WK;
    int i = blockIdx.x * blockDim.x + threadIdx.x;
    const int str = gridDim.x * blockDim.x;
    for (; i < total; i += str) {
        const float4* s; float4* d; int off = i;
        if (off < N4_X) { s = x; d = (float4*)g_xr; }
        else if ((off -= N4_X) < N4_WQ) { s = wq; d = (float4*)g_wqr; }
        else if ((off -= N4_WQ) < N4_WK) { s = wk; d = (float4*)g_wkr; }
        else if ((off -= N4_WK) < N4_WK) { s = wv; d = (float4*)g_wvr; }
        else { off -= N4_WK; s = wo; d = (float4*)g_wor; }
        float4 v = s[off];
        d[off] = make_float4(f2tff(v.x), f2tff(v.y), f2tff(v.z), f2tff(v.w));
    }
}

// ---------------- tf32 NT GEMM body (3-stage cp.async, 4 warps) --------------
// block 128x128, BK=32, 128 threads = 4 warps (2m x 2n), warp tile 64x64.
#define GS 36
#define GSTG (128*GS)
__device__ __forceinline__ void gemm_body(const float* __restrict__ A,
                                          const float* __restrict__ W,
                                          float* __restrict__ out,
                                          int N, int K, int m0, int n0) {
    extern __shared__ float gsm[];
    float* smA = gsm;
    float* smB = gsm + 3 * GSTG;

    const int tid  = threadIdx.x;       // 0..127
    const int lane = tid & 31;
    const int wid  = tid >> 5;          // 0..3
    const int wm = (wid >> 1) * 64, wn = (wid & 1) * 64;
    const int g = lane >> 2, t = lane & 3;

    const int aoff = (wm + (lane & 15)) * GS + (lane >> 4) * 4;
    const int boff = (wn + (lane & 7) + ((lane >> 4) << 3)) * GS + ((lane >> 3) & 1) * 4;

    float acc[4][8][4];
#pragma unroll
    for (int i = 0; i < 4; i++)
#pragma unroll
        for (int j = 0; j < 8; j++)
#pragma unroll
            for (int e = 0; e < 4; e++) acc[i][j][e] = 0.f;

    const int nt = K / 32;
#pragma unroll
    for (int p = 0; p < 2; p++) {
        int k0 = p * 32;
#pragma unroll
        for (int l = 0; l < 8; l++) {
            int idx = tid + l * 128;
            int row = idx >> 3, c = idx & 7;
            cpa16(&smA[p * GSTG + row * GS + c * 4], A + (size_t)(m0 + row) * K + k0 + c * 4);
            cpa16(&smB[p * GSTG + row * GS + c * 4], W + (size_t)(n0 + row) * K + k0 + c * 4);
        }
        cp_commit();
    }
    cp_wait<1>();
    __syncthreads();

    int s = 0;
    for (int i = 0; i < nt; i++) {
        if (i + 2 < nt) {
            int k0 = (i + 2) * 32;
            int sn = (s + 2) % 3;
#pragma unroll
            for (int l = 0; l < 8; l++) {
                int idx = tid + l * 128;
                int row = idx >> 3, c = idx & 7;
                cpa16(&smA[sn * GSTG + row * GS + c * 4], A + (size_t)(m0 + row) * K + k0 + c * 4);
                cpa16(&smB[sn * GSTG + row * GS + c * 4], W + (size_t)(n0 + row) * K + k0 + c * 4);
            }
            cp_commit();
        }
        const float* pA = smA + s * GSTG + aoff;
        const float* pB = smB + s * GSTG + boff;
#pragma unroll
        for (int ks = 0; ks < 4; ks++) {
            const int kk = ks * 8;
            unsigned a[4][4];
#pragma unroll
            for (int ii = 0; ii < 4; ii++)
                ldsm4(a[ii][0], a[ii][1], a[ii][2], a[ii][3], pA + ii * 16 * GS + kk);
            unsigned b[8][2];
#pragma unroll
            for (int jp = 0; jp < 4; jp++)
                ldsm4(b[2*jp][0], b[2*jp][1], b[2*jp+1][0], b[2*jp+1][1],
                      pB + jp * 16 * GS + kk);
#pragma unroll
            for (int ii = 0; ii < 4; ii++)
#pragma unroll
                for (int j = 0; j < 8; j++)
                    mma_tf32(acc[ii][j][0], acc[ii][j][1], acc[ii][j][2], acc[ii][j][3],
                             a[ii][0], a[ii][1], a[ii][2], a[ii][3], b[j][0], b[j][1]);
        }
        if (i + 2 < nt) cp_wait<1>(); else cp_wait<0>();
        __syncthreads();
        s = (s + 1) % 3;
    }
#pragma unroll
    for (int i = 0; i < 4; i++) {
        int r = m0 + wm + i * 16 + g;
#pragma unroll
        for (int j = 0; j < 8; j++) {
            int c = n0 + wn + j * 8 + 2 * t;
            *(float2*)(out + (size_t)r * N + c) = make_float2(acc[i][j][0], acc[i][j][1]);
            *(float2*)(out + (size_t)(r + 8) * N + c) = make_float2(acc[i][j][2], acc[i][j][3]);
        }
    }
}

__global__ __launch_bounds__(128) void gemm_qkv() {
    const int bid = blockIdx.x;
    if (bid < 512) {
        gemm_body(g_xr, g_wqr, g_qraw, CC, CC, (bid >> 3) * 128, (bid & 7) * 128);
    } else {
        const int r = bid - 512;
        const bool isv = (r & 3) >= 2;
        gemm_body(g_xr, isv ? g_wvr : g_wkr, isv ? g_vraw : g_kraw,
                  NKV * HD, CC, (r >> 2) * 128, (r & 1) * 128);
    }
}

__global__ __launch_bounds__(128) void gemm_tf32(const float* __restrict__ A,
                                                 const float* __restrict__ W,
                                                 float* __restrict__ out,
                                                 int N, int K) {
    gemm_body(A, W, out, N, K, blockIdx.y * 128, blockIdx.x * 128);
}

// ---------------- merged rope/rmsnorm + V gate/transpose ---------------------
__device__ __forceinline__ void rope_norm(const float* __restrict__ in,
                                          float* __restrict__ outp,
                                          int t, int lane, float mult,
                                          const float* __restrict__ cosp,
                                          const float* __restrict__ sinp) {
    float x1 = in[lane];
    float x2 = in[32 + lane];
    float c  = cosp[t * 32 + lane];
    float s  = sinp[t * 32 + lane];
    float o1 =  x1 * c + x2 * s;
    float o2 = -x1 * s + x2 * c;
    float ss = o1 * o1 + o2 * o2;
#pragma unroll
    for (int off = 16; off; off >>= 1) ss += __shfl_xor_sync(0xffffffffu, ss, off);
    float r = rsqrtf(ss * (1.0f / HD) + 1e-6f) * mult;
    outp[lane]      = f2tff(o1 * r);
    outp[32 + lane] = f2tff(o2 * r);
}

// grid NTOK + 1024: first NTOK blocks = rope (1 token each);
// last 1024 = V gate-add + transpose (32 tokens x 1 kv head each, own gates).
__global__ __launch_bounds__(256) void post_vt(const float* __restrict__ x,
                                               const float* __restrict__ ve,
                                               const float* __restrict__ cosp,
                                               const float* __restrict__ sinp,
                                               const float* __restrict__ wgate) {
    __shared__ float st[32 * 65];
    __shared__ float gates[32];

    const int bid  = blockIdx.x;
    const int tid  = threadIdx.x;
    const int w    = tid >> 5;
    const int lane = tid & 31;

    if (bid < NTOK) {                       // ---- rope/rmsnorm for q and k ----
        const int n = bid;
        const int b = n / TT;
        const int t = n % TT;
        const float QMULT = 1.15f * 0.125f * 1.4426950408889634f;
#pragma unroll
        for (int h = w; h < NH; h += 8) {
            size_t obase = (((size_t)b * NH + h) * TT + t) * HD;
            rope_norm(g_qraw + (size_t)n * CC + h * HD, g_qn + obase, t, lane,
                      QMULT, cosp, sinp);
        }
        if (w < 4) {
            int h = w;
            size_t obase = (((size_t)b * NKV + h) * TT + t) * HD;
            rope_norm(g_kraw + (size_t)n * NKV * HD + h * HD, g_kn + obase, t, lane,
                      1.15f, cosp, sinp);
        }
        return;
    }

    // ---- V: gate + add + transpose to [B,KV,D,T] ----
    const int r  = bid - NTOK;              // 0..1023
    const int t0 = (r & 63) * 32;
    const int bkv = r >> 6;                 // 0..15
    const int b  = bkv >> 2;
    const int kv = bkv & 3;

    if (tid < 32) {                         // per-token gate (12-dot + sigmoid)
        size_t n = (size_t)b * TT + t0 + tid;
        float gsum = 0.f;
#pragma unroll
        for (int c = 0; c < GATE_CH; c++)
            gsum += x[n * CC + c] * wgate[kv * GATE_CH + c];
        gates[tid] = 3.f / (1.f + __expf(-gsum));
    }
    __syncthreads();

#pragma unroll
    for (int l = 0; l < 2; l++) {
        int idx = tid + l * 256;
        int tt = idx >> 4, c4 = idx & 15;
        size_t n = (size_t)b * TT + t0 + tt;
        size_t base = n * (NKV * HD) + kv * HD + c4 * 4;
        float4 vr = *(const float4*)(g_vraw + base);
        float4 vv = *(const float4*)(ve + base);
        float  gg = gates[tt];
        st[tt * 65 + c4 * 4 + 0] = f2tff(vr.x + gg * vv.x);
        st[tt * 65 + c4 * 4 + 1] = f2tff(vr.y + gg * vv.y);
        st[tt * 65 + c4 * 4 + 2] = f2tff(vr.z + gg * vv.z);
        st[tt * 65 + c4 * 4 + 3] = f2tff(vr.w + gg * vv.w);
    }
    __syncthreads();
#pragma unroll
    for (int l = 0; l < 2; l++) {
        int idx = tid + l * 256;
        int d = idx >> 3, tc = idx & 7;
        float4 o = make_float4(st[(tc * 4 + 0) * 65 + d], st[(tc * 4 + 1) * 65 + d],
                               st[(tc * 4 + 2) * 65 + d], st[(tc * 4 + 3) * 65 + d]);
        *(float4*)(g_vt + ((size_t)bkv * HD + d) * TT + t0 + tc * 4) = o;
    }
}

// ---------------- tensor-core sliding-window flash attention -----------------
// grid (T/128, B*H), 128 threads = 4 warps; warp w owns q rows w*32..w*32+31.
#define AS 68
#define QT 128
#define KVSTG (64 * AS)
__global__ __launch_bounds__(128) void attn_tc(const float* __restrict__ q,
                                               const float* __restrict__ k,
                                               const float* __restrict__ v,   // [B,KV,D,T]
                                               const int* __restrict__ winp,
                                               float* __restrict__ y) {
    extern __shared__ float sm[];
    float* sQ = sm;
    float* sP = sm;
    float* sK = sm + QT * AS;
    float* sV = sK + 2 * KVSTG;

    const int tid  = threadIdx.x;
    const int lane = tid & 31;
    const int wid  = tid >> 5;
    const int g = lane >> 2, t = lane & 3;

    const int qt = blockIdx.x;
    const int bh = blockIdx.y;
    const int b  = bh >> 4;
    const int h  = bh & 15;
    const int kvh = h >> 2;
    const int q0  = qt * QT;
    const int win = winp[0];

    int kstart = q0 - win; if (kstart < 0) kstart = 0;
    const int kt0 = kstart >> 6;
    const int kt1 = (q0 + QT - 1) >> 6;

    const size_t kvbase = ((size_t)b * NKV + kvh) * TT;
    const size_t vtbase = ((size_t)b * NKV + kvh) * HD;

    const int ldsmB  = ((lane & 7) + ((lane >> 4) << 3)) * AS + ((lane >> 3) & 1) * 4;
    const int ldsmA0 = (wid * 32 + (lane & 15)) * AS + (lane >> 4) * 4;
    const int ldsmA1 = ldsmA0 + 16 * AS;

    {
        const int k0 = kt0 * 64;
#pragma unroll
        for (int l = 0; l < 8; l++) {
            int idx = tid + l * 128;
            int row = idx >> 4, c4 = idx & 15;
            cpa16(&sK[row * AS + c4 * 4], k + (kvbase + k0 + row) * HD + c4 * 4);
            cpa16(&sV[row * AS + c4 * 4], v + (vtbase + row) * TT + k0 + c4 * 4);
        }
        cp_commit();
    }

    {
        size_t qb = (((size_t)b * NH + h) * TT + q0) * HD;
#pragma unroll
        for (int l = 0; l < 16; l++) {
            int idx = tid + l * 128;
            int row = idx >> 4, c4 = idx & 15;
            *(float4*)&sQ[row * AS + c4 * 4] =
                *(const float4*)(q + qb + (size_t)row * HD + c4 * 4);
        }
    }
    __syncthreads();

    unsigned qa[2][8][4];
#pragma unroll
    for (int ks = 0; ks < 8; ks++) {
        ldsm4(qa[0][ks][0], qa[0][ks][1], qa[0][ks][2], qa[0][ks][3], sQ + ldsmA0 + ks * 8);
        ldsm4(qa[1][ks][0], qa[1][ks][1], qa[1][ks][2], qa[1][ks][3], sQ + ldsmA1 + ks * 8);
    }

    float accO[2][8][4];
#pragma unroll
    for (int rb = 0; rb < 2; rb++)
#pragma unroll
        for (int j = 0; j < 8; j++)
#pragma unroll
            for (int e = 0; e < 4; e++) accO[rb][j][e] = 0.f;
    float mrow[4] = {-1e30f, -1e30f, -1e30f, -1e30f};
    float lrow[4] = {0.f, 0.f, 0.f, 0.f};

    const int rw   = wid * 32 + g;
    const int rmin = q0 + wid * 32;
    const int rmax = rmin + 31;
    const int rr[4] = {q0 + rw, q0 + rw + 8, q0 + rw + 16, q0 + rw + 24};

    int stage = 0;
    for (int kt = kt0; kt <= kt1; kt++, stage ^= 1) {
        const int k0 = kt * 64;
        cp_wait<0>();
        __syncthreads();
        if (kt < kt1) {
            const int nk0 = (kt + 1) * 64;
            float* dK = sK + (stage ^ 1) * KVSTG;
            float* dV = sV + (stage ^ 1) * KVSTG;
#pragma unroll
            for (int l = 0; l < 8; l++) {
                int idx = tid + l * 128;
                int row = idx >> 4, c4 = idx & 15;
                cpa16(&dK[row * AS + c4 * 4], k + (kvbase + nk0 + row) * HD + c4 * 4);
                cpa16(&dV[row * AS + c4 * 4], v + (vtbase + row) * TT + nk0 + c4 * 4);
            }
            cp_commit();
        }
        if (k0 > rmax || k0 + 63 < rmin - win) continue;

        const float* cK = sK + stage * KVSTG;
        const float* cV = sV + stage * KVSTG;

        float s[2][8][4];
#pragma unroll
        for (int rb = 0; rb < 2; rb++)
#pragma unroll
            for (int j = 0; j < 8; j++)
#pragma unroll
                for (int e = 0; e < 4; e++) s[rb][j][e] = 0.f;
#pragma unroll
        for (int ks = 0; ks < 8; ks++) {
            const int kk = ks * 8;
            unsigned bb[8][2];
#pragma unroll
            for (int jp = 0; jp < 4; jp++)
                ldsm4(bb[2*jp][0], bb[2*jp][1], bb[2*jp+1][0], bb[2*jp+1][1],
                      cK + ldsmB + jp * 16 * AS + kk);
#pragma unroll
            for (int rb = 0; rb < 2; rb++)
#pragma unroll
                for (int j = 0; j < 8; j++)
                    mma_tf32(s[rb][j][0], s[rb][j][1], s[rb][j][2], s[rb][j][3],
                             qa[rb][ks][0], qa[rb][ks][1], qa[rb][ks][2], qa[rb][ks][3],
                             bb[j][0], bb[j][1]);
        }

        bool full = (k0 + 63 <= rmin) && (rmax - k0 <= win);
        if (!full) {
#pragma unroll
            for (int rb = 0; rb < 2; rb++)
#pragma unroll
                for (int j = 0; j < 8; j++) {
                    int c0 = k0 + j * 8 + 2 * t;
                    int da = rr[2*rb]   - c0;
                    int db = rr[2*rb+1] - c0;
                    if (!(da     >= 0 && da     <= win)) s[rb][j][0] = -1e30f;
                    if (!(da - 1 >= 0 && da - 1 <= win)) s[rb][j][1] = -1e30f;
                    if (!(db     >= 0 && db     <= win)) s[rb][j][2] = -1e30f;
                    if (!(db - 1 >= 0 && db - 1 <= win)) s[rb][j][3] = -1e30f;
                }
        }

        float mt[4] = {-1e30f, -1e30f, -1e30f, -1e30f};
#pragma unroll
        for (int rb = 0; rb < 2; rb++)
#pragma unroll
            for (int j = 0; j < 8; j++) {
                mt[2*rb]   = fmaxf(mt[2*rb],   fmaxf(s[rb][j][0], s[rb][j][1]));
                mt[2*rb+1] = fmaxf(mt[2*rb+1], fmaxf(s[rb][j][2], s[rb][j][3]));
            }
#pragma unroll
        for (int r = 0; r < 4; r++) {
            mt[r] = fmaxf(mt[r], __shfl_xor_sync(0xffffffffu, mt[r], 1));
            mt[r] = fmaxf(mt[r], __shfl_xor_sync(0xffffffffu, mt[r], 2));
        }
        float mn[4], al[4], rs[4];
#pragma unroll
        for (int r = 0; r < 4; r++) {
            mn[r] = fmaxf(mrow[r], mt[r]);
            al[r] = exp2f(mrow[r] - mn[r]);
            rs[r] = 0.f;
        }
#pragma unroll
        for (int rb = 0; rb < 2; rb++)
#pragma unroll
            for (int j = 0; j < 8; j++) {
                float p0 = exp2f(s[rb][j][0] - mn[2*rb]);
                float p1 = exp2f(s[rb][j][1] - mn[2*rb]);
                float p2 = exp2f(s[rb][j][2] - mn[2*rb+1]);
                float p3 = exp2f(s[rb][j][3] - mn[2*rb+1]);
                rs[2*rb]   += p0 + p1;
                rs[2*rb+1] += p2 + p3;
                int cb = j * 8 + 2 * t;
                int rbase = rw + rb * 16;
                *(float2*)&sP[rbase * AS + cb]       = make_float2(f2tff(p0), f2tff(p1));
                *(float2*)&sP[(rbase + 8) * AS + cb] = make_float2(f2tff(p2), f2tff(p3));
            }
#pragma unroll
        for (int r = 0; r < 4; r++) {
            rs[r] += __shfl_xor_sync(0xffffffffu, rs[r], 1);
            rs[r] += __shfl_xor_sync(0xffffffffu, rs[r], 2);
            lrow[r] = lrow[r] * al[r] + rs[r];
            mrow[r] = mn[r];
        }
#pragma unroll
        for (int rb = 0; rb < 2; rb++)
#pragma unroll
            for (int j = 0; j < 8; j++) {
                accO[rb][j][0] *= al[2*rb];   accO[rb][j][1] *= al[2*rb];
                accO[rb][j][2] *= al[2*rb+1]; accO[rb][j][3] *= al[2*rb+1];
            }
        __syncwarp();

#pragma unroll
        for (int ks = 0; ks < 8; ks++) {
            const int kk = ks * 8;
            unsigned pa[2][4];
            ldsm4(pa[0][0], pa[0][1], pa[0][2], pa[0][3], sP + ldsmA0 + kk);
            ldsm4(pa[1][0], pa[1][1], pa[1][2], pa[1][3], sP + ldsmA1 + kk);
            unsigned bb[8][2];
#pragma unroll
            for (int jp = 0; jp < 4; jp++)
                ldsm4(bb[2*jp][0], bb[2*jp][1], bb[2*jp+1][0], bb[2*jp+1][1],
                      cV + ldsmB + jp * 16 * AS + kk);
#pragma unroll
            for (int rb = 0; rb < 2; rb++)
#pragma unroll
                for (int j = 0; j < 8; j++)
                    mma_tf32(accO[rb][j][0], accO[rb][j][1], accO[rb][j][2], accO[rb][j][3],
                             pa[rb][0], pa[rb][1], pa[rb][2], pa[rb][3],
                             bb[j][0], bb[j][1]);
        }
    }

    float il[4];
#pragma unroll
    for (int r = 0; r < 4; r++) il[r] = 1.0f / lrow[r];
#pragma unroll
    for (int rb = 0; rb < 2; rb++)
#pragma unroll
        for (int j = 0; j < 8; j++) {
            int d = h * HD + j * 8 + 2 * t;
            *(float2*)(y + ((size_t)b * TT + rr[2*rb]) * CC + d) =
                make_float2(f2tff(accO[rb][j][0] * il[2*rb]),
                            f2tff(accO[rb][j][1] * il[2*rb]));
            *(float2*)(y + ((size_t)b * TT + rr[2*rb+1]) * CC + d) =
                make_float2(f2tff(accO[rb][j][2] * il[2*rb+1]),
                            f2tff(accO[rb][j][3] * il[2*rb+1]));
        }
}

// ---------------- launcher ---------------------------------------------------
extern "C" void kernel_launch(void* const* d_in, const int* in_sizes, int n_in,
                              void* d_out, int out_size) {
    const float* x    = (const float*)d_in[0];
    const float* ve   = (const float*)d_in[1];
    const float* cosp = (const float*)d_in[2];
    const float* sinp = (const float*)d_in[3];
    const float* wq   = (const float*)d_in[4];
    const float* wk   = (const float*)d_in[5];
    const float* wv   = (const float*)d_in[6];
    const float* wo   = (const float*)d_in[7];
    const float* wg   = (const float*)d_in[8];
    const int*   win  = (const int*)d_in[9];
    float* out = (float*)d_out;

    float *qn, *kn, *vt, *att, *wor;
    cudaGetSymbolAddress((void**)&qn,  g_qn);
    cudaGetSymbolAddress((void**)&kn,  g_kn);
    cudaGetSymbolAddress((void**)&vt,  g_vt);
    cudaGetSymbolAddress((void**)&att, g_att);
    cudaGetSymbolAddress((void**)&wor, g_wor);

    cvt_all<<<2368, 256>>>((const float4*)x, (const float4*)wq, (const float4*)wk,
                           (const float4*)wv, (const float4*)wo);

    int gsmem = 6 * GSTG * (int)sizeof(float);  // 110592 B
    cudaFuncSetAttribute(gemm_qkv,  cudaFuncAttributeMaxDynamicSharedMemorySize, gsmem);
    cudaFuncSetAttribute(gemm_tf32, cudaFuncAttributeMaxDynamicSharedMemorySize, gsmem);

    gemm_qkv<<<768, 128, gsmem>>>();

    // merged rope + V gate/transpose (one launch)
    post_vt<<<NTOK + 1024, 256>>>(x, ve, cosp, sinp, wg);

    int smem = (QT * AS + 4 * KVSTG) * (int)sizeof(float);  // 104448 B
    cudaFuncSetAttribute(attn_tc, cudaFuncAttributeMaxDynamicSharedMemorySize, smem);
    attn_tc<<<dim3(TT / QT, BB * NH), 128, smem>>>(qn, kn, vt, win, att);

    gemm_tf32<<<dim3(CC / 128, NTOK / 128), 128, gsmem>>>(att, wor, out, CC, CC);
}